// round 3
// baseline (speedup 1.0000x reference)
#include <cuda_runtime.h>

// circ_layer: out = mm*x + mm + x, mm[b,i] = sum_j x[b,j] * w[(j-i) mod 1024]
// = circular correlation => IDFT( FFT(x_row) * conj(FFT(w)) ), all fp32.
// Two real tokens packed per complex FFT (re = token a, im = token b).

static constexpr int N_F  = 1024;
static constexpr int NTOK = 65536;
static constexpr int TPB  = 256;
static constexpr int SPAD = N_F + (N_F >> 5);   // 1056 floats per plane

__device__ float2 g_tw[N_F];   // e^{-2*pi*i*k/N}
__device__ float2 g_wc[N_F];   // conj(FFT_fwd(w))/N, in the forward routine's output order

__device__ __forceinline__ int sp(int i) { return i + (i >> 5); }

struct C2 { float re, im; };

__device__ __forceinline__ C2 mkc(float r, float i) { C2 c; c.re = r; c.im = i; return c; }
__device__ __forceinline__ C2 cadd(C2 a, C2 b) { return mkc(a.re + b.re, a.im + b.im); }
__device__ __forceinline__ C2 csub(C2 a, C2 b) { return mkc(a.re - b.re, a.im - b.im); }
// a * w
__device__ __forceinline__ C2 cmul(C2 a, float2 w) {
    return mkc(fmaf(a.re, w.x, -a.im * w.y), fmaf(a.re, w.y, a.im * w.x));
}
// a * conj(w)
__device__ __forceinline__ C2 cmulc(C2 a, float2 w) {
    return mkc(fmaf(a.re, w.x, a.im * w.y), fmaf(a.im, w.x, -a.re * w.y));
}

// Forward radix-4 DIF butterfly. Inputs a_m at positions base+m*s, outputs
// X_k * w_k written back to base+k*s. W4^{mk} = (-i)^{mk}.
__device__ __forceinline__ void bf_fwd(C2 v[4], float2 w1, float2 w2, float2 w3) {
    C2 t0 = cadd(v[0], v[2]), t1 = cadd(v[1], v[3]);
    C2 t2 = csub(v[0], v[2]), t3 = csub(v[1], v[3]);
    C2 x1 = mkc(t2.re + t3.im, t2.im - t3.re);   // t2 - i*t3
    C2 x3 = mkc(t2.re - t3.im, t2.im + t3.re);   // t2 + i*t3
    v[0] = cadd(t0, t1);
    v[1] = cmul(x1, w1);
    v[2] = cmul(csub(t0, t1), w2);
    v[3] = cmul(x3, w3);
}
__device__ __forceinline__ void bf_fwd1(C2 v[4]) {  // unit twiddles (last stage)
    C2 t0 = cadd(v[0], v[2]), t1 = cadd(v[1], v[3]);
    C2 t2 = csub(v[0], v[2]), t3 = csub(v[1], v[3]);
    v[0] = cadd(t0, t1);
    v[1] = mkc(t2.re + t3.im, t2.im - t3.re);
    v[2] = csub(t0, t1);
    v[3] = mkc(t2.re - t3.im, t2.im + t3.re);
}
// Exact inverse of bf_fwd (un-twiddle, then 4-pt DFT with +i; carries factor 4)
__device__ __forceinline__ void bf_inv(C2 v[4], float2 w1, float2 w2, float2 w3) {
    C2 z1 = cmulc(v[1], w1), z2 = cmulc(v[2], w2), z3 = cmulc(v[3], w3);
    C2 t0 = cadd(v[0], z2), t1 = cadd(z1, z3);
    C2 t2 = csub(v[0], z2), t3 = csub(z1, z3);
    v[0] = cadd(t0, t1);
    v[1] = mkc(t2.re - t3.im, t2.im + t3.re);    // t2 + i*t3
    v[2] = csub(t0, t1);
    v[3] = mkc(t2.re + t3.im, t2.im - t3.re);    // t2 - i*t3
}
__device__ __forceinline__ void bf_inv1(C2 v[4]) {
    C2 t0 = cadd(v[0], v[2]), t1 = cadd(v[1], v[3]);
    C2 t2 = csub(v[0], v[2]), t3 = csub(v[1], v[3]);
    v[0] = cadd(t0, t1);
    v[1] = mkc(t2.re - t3.im, t2.im + t3.re);
    v[2] = csub(t0, t1);
    v[3] = mkc(t2.re + t3.im, t2.im - t3.re);
}

__device__ __forceinline__ void st4(float* sre, float* sim, const C2 v[4], int base, int stride) {
#pragma unroll
    for (int m = 0; m < 4; m++) {
        int a = sp(base + stride * m);
        sre[a] = v[m].re; sim[a] = v[m].im;
    }
}
__device__ __forceinline__ void ld4(const float* sre, const float* sim, C2 v[4], int base, int stride) {
#pragma unroll
    for (int m = 0; m < 4; m++) {
        int a = sp(base + stride * m);
        v[m].re = sre[a]; v[m].im = sim[a];
    }
}

struct TW { float2 t1[3], t2[3], t3[3], t4[3]; };

__device__ __forceinline__ void load_tw(int t, TW& tw) {
    int j2 = t & 63, j3 = t & 15, j4 = t & 3;
#pragma unroll
    for (int k = 0; k < 3; k++) {
        tw.t1[k] = g_tw[(k + 1) * t];           // stage L=1024, f=1,  j=t
        tw.t2[k] = g_tw[4  * (k + 1) * j2];     // stage L=256,  f=4
        tw.t3[k] = g_tw[16 * (k + 1) * j3];     // stage L=64,   f=16
        tw.t4[k] = g_tw[64 * (k + 1) * j4];     // stage L=16,   f=64
    }
}

// Bases for each stage's element set {base + stride*m}
struct POS { int c1, c2, c3, c4, c5; };
__device__ __forceinline__ void make_pos(int t, POS& p) {
    p.c1 = t;                                // stride 256
    p.c2 = ((t >> 6) << 8) | (t & 63);       // stride 64
    p.c3 = ((t >> 4) << 6) | (t & 15);       // stride 16
    p.c4 = ((t >> 2) << 4) | (t & 3);        // stride 4
    p.c5 = 4 * t;                            // stride 1
}

// Forward FFT: entry with v holding elements {t + 256m}; exit with v holding
// output (digit-reversed order) at logical positions {4t + m}.
__device__ __forceinline__ void fft_fwd(float* sre, float* sim, C2 v[4],
                                        const POS& p, const TW& tw) {
    bf_fwd(v, tw.t1[0], tw.t1[1], tw.t1[2]);
    st4(sre, sim, v, p.c1, 256); __syncthreads(); ld4(sre, sim, v, p.c2, 64);
    bf_fwd(v, tw.t2[0], tw.t2[1], tw.t2[2]);
    st4(sre, sim, v, p.c2, 64);  __syncthreads(); ld4(sre, sim, v, p.c3, 16);
    bf_fwd(v, tw.t3[0], tw.t3[1], tw.t3[2]);
    st4(sre, sim, v, p.c3, 16);  __syncthreads(); ld4(sre, sim, v, p.c4, 4);
    bf_fwd(v, tw.t4[0], tw.t4[1], tw.t4[2]);
    st4(sre, sim, v, p.c4, 4);   __syncthreads(); ld4(sre, sim, v, p.c5, 1);
    bf_fwd1(v);
}

// Inverse (exact stage-by-stage undo, carries overall factor 4^5 = N):
// entry with v at {4t + m}; exit with v at {t + 256m} in natural (time) order.
__device__ __forceinline__ void fft_inv(float* sre, float* sim, C2 v[4],
                                        const POS& p, const TW& tw) {
    bf_inv1(v);
    st4(sre, sim, v, p.c5, 1);   __syncthreads(); ld4(sre, sim, v, p.c4, 4);
    bf_inv(v, tw.t4[0], tw.t4[1], tw.t4[2]);
    st4(sre, sim, v, p.c4, 4);   __syncthreads(); ld4(sre, sim, v, p.c3, 16);
    bf_inv(v, tw.t3[0], tw.t3[1], tw.t3[2]);
    st4(sre, sim, v, p.c3, 16);  __syncthreads(); ld4(sre, sim, v, p.c2, 64);
    bf_inv(v, tw.t2[0], tw.t2[1], tw.t2[2]);
    st4(sre, sim, v, p.c2, 64);  __syncthreads(); ld4(sre, sim, v, p.c1, 256);
    bf_inv(v, tw.t1[0], tw.t1[1], tw.t1[2]);
}

// ---------------- init kernels ----------------

__global__ void k_tw_init() {
    int k = blockIdx.x * blockDim.x + threadIdx.x;   // <<<4,256>>>
    float s, c;
    sincospif((float)k / 512.0f, &s, &c);            // angle = pi*k/512 = 2*pi*k/1024
    g_tw[k] = make_float2(c, -s);                    // e^{-2*pi*i*k/N}
}

__global__ void __launch_bounds__(TPB) k_wc_init(const float* __restrict__ w) {
    __shared__ float sre[SPAD], sim[SPAD];
    int t = threadIdx.x;
    POS p; make_pos(t, p);
    TW tw; load_tw(t, tw);
    C2 v[4];
#pragma unroll
    for (int m = 0; m < 4; m++) { v[m].re = w[t + 256 * m]; v[m].im = 0.0f; }
    fft_fwd(sre, sim, v, p, tw);
    // Wc = conj(FFT(w)) / N  (1/N for the IDFT; fft_inv contributes the other N)
#pragma unroll
    for (int m = 0; m < 4; m++)
        g_wc[4 * t + m] = make_float2(v[m].re * (1.0f / 1024.0f),
                                      -v[m].im * (1.0f / 1024.0f));
}

// ---------------- main kernel ----------------

__global__ void __launch_bounds__(TPB, 4) k_main(const float* __restrict__ x,
                                                 float* __restrict__ out) {
    __shared__ float sre[SPAD], sim[SPAD];
    int t = threadIdx.x;
    long base = (long)blockIdx.x * (2 * N_F);

    const float4* xa4 = (const float4*)(x + base);
    const float4* xb4 = (const float4*)(x + base + N_F);
    float4 va = xa4[t];     // token a elements 4t..4t+3 (kept for epilogue)
    float4 vb = xb4[t];     // token b elements 4t..4t+3

    POS p; make_pos(t, p);
    TW tw; load_tw(t, tw);

    // natural-order store: z = x_a + i*x_b
    {
        float ar[4] = { va.x, va.y, va.z, va.w };
        float br[4] = { vb.x, vb.y, vb.z, vb.w };
#pragma unroll
        for (int m = 0; m < 4; m++) {
            int a = sp(4 * t + m);
            sre[a] = ar[m]; sim[a] = br[m];
        }
    }
    __syncthreads();

    C2 v[4];
    ld4(sre, sim, v, p.c1, 256);        // stage-1 element set {t + 256m}

    fft_fwd(sre, sim, v, p, tw);

    // pointwise: Z * conj(W)/N, matching permuted order (same routine everywhere)
#pragma unroll
    for (int m = 0; m < 4; m++) {
        float2 wc = g_wc[4 * t + m];
        v[m] = cmul(v[m], wc);
    }

    fft_inv(sre, sim, v, p, tw);

    // v at {t + 256m}; move to natural order for coalesced epilogue
    st4(sre, sim, v, p.c1, 256);
    __syncthreads();

    float4 oa, ob;
    {
        float ar[4] = { va.x, va.y, va.z, va.w };
        float br[4] = { vb.x, vb.y, vb.z, vb.w };
        float oav[4], obv[4];
#pragma unroll
        for (int m = 0; m < 4; m++) {
            int a = sp(4 * t + m);
            float mma = sre[a];   // mm for token a
            float mmb = sim[a];   // mm for token b
            oav[m] = fmaf(mma, ar[m], mma + ar[m]);   // mm*x + mm + x
            obv[m] = fmaf(mmb, br[m], mmb + br[m]);
        }
        oa = make_float4(oav[0], oav[1], oav[2], oav[3]);
        ob = make_float4(obv[0], obv[1], obv[2], obv[3]);
    }
    ((float4*)(out + base))[t] = oa;
    ((float4*)(out + base + N_F))[t] = ob;
}

extern "C" void kernel_launch(void* const* d_in, const int* in_sizes, int n_in,
                              void* d_out, int out_size) {
    const float* x = (const float*)d_in[0];     // [65536, 1024] fp32
    const float* w = (const float*)d_in[1];     // [1024] fp32
    float* out = (float*)d_out;                 // [65536, 1024] fp32

    k_tw_init<<<4, 256>>>();
    k_wc_init<<<1, TPB>>>(w);
    k_main<<<NTOK / 2, TPB>>>(x, out);
}

// round 4
// speedup vs baseline: 2.4472x; 2.4472x over previous
#include <cuda_runtime.h>

// circ_layer: out = mm*x + mm + x, mm[b,i] = sum_j x[b,j] * w[(j-i) mod 1024]
// = circular correlation => IDFT( FFT(x_row) * conj(FFT(w)) ), all fp32.
//
// Four-step FFT: 1024 = 32 x 32. One warp handles TWO tokens packed as one
// complex sequence (re = token a, im = token b). Each thread holds 32 complex
// values in registers; length-32 FFTs run in registers with compile-time
// twiddles; only two 32x32 smem transposes per direction. No __syncthreads.

static constexpr int WPB  = 4;            // warps per block
static constexpr int TPB  = WPB * 32;
static constexpr int NTOK = 65536;

__device__ __align__(16) float2 g_wc[1024];   // conj(FFT(w))/N, pipeline layout

__device__ __forceinline__ int br5(int x) {
    return ((x & 1) << 4) | ((x & 2) << 2) | (x & 4) | ((x & 8) >> 2) | ((x & 16) >> 4);
}

__device__ __forceinline__ float twc(int t) {
    constexpr float C[16] = {
        1.0f,                   0.9807852804032304f,  0.9238795325112867f,  0.8314696123025452f,
        0.7071067811865476f,    0.5555702330196022f,  0.3826834323650898f,  0.1950903220161283f,
        0.0f,                  -0.1950903220161283f, -0.3826834323650898f, -0.5555702330196022f,
       -0.7071067811865476f,   -0.8314696123025452f, -0.9238795325112867f, -0.9807852804032304f };
    return C[t];
}
__device__ __forceinline__ float tws(int t) {
    constexpr float S[16] = {
        0.0f,                   0.1950903220161283f,  0.3826834323650898f,  0.5555702330196022f,
        0.7071067811865476f,    0.8314696123025452f,  0.9238795325112867f,  0.9807852804032304f,
        1.0f,                   0.9807852804032304f,  0.9238795325112867f,  0.8314696123025452f,
        0.7071067811865476f,    0.5555702330196022f,  0.3826834323650898f,  0.1950903220161283f };
    return S[t];
}

// (xr,xi) = (dr,di) * e^{-+2*pi*i*t/32}  (forward: e^{-}, inverse: e^{+})
template<bool INV>
__device__ __forceinline__ void rot(int t, float dr, float di, float& xr, float& xi) {
    if (t == 0)      { xr = dr; xi = di; }
    else if (t == 8) {
        if (!INV) { xr = di;  xi = -dr; }   // * (-i)
        else      { xr = -di; xi =  dr; }   // * (+i)
    } else {
        float c = twc(t), s = tws(t);
        if (!INV) { xr = fmaf(dr, c,  di * s); xi = fmaf(di, c, -dr * s); }
        else      { xr = fmaf(dr, c, -di * s); xi = fmaf(di, c,  dr * s); }
    }
}

// DIF radix-2 length-32 FFT in registers: natural in, bit-reversed out.
template<bool INV>
__device__ __forceinline__ void fft32_dif(float zr[32], float zi[32]) {
#pragma unroll
    for (int s = 0; s < 5; s++) {
        const int len = 32 >> s, half = len >> 1;
#pragma unroll
        for (int g = 0; g < 32; g += len)
#pragma unroll
            for (int j = 0; j < half; j++) {
                const int a = g + j, b = a + half;
                float dr = zr[a] - zr[b], di = zi[a] - zi[b];
                zr[a] += zr[b]; zi[a] += zi[b];
                rot<INV>(j << s, dr, di, zr[b], zi[b]);
            }
    }
}

// DIT radix-2 length-32 inverse FFT: bit-reversed in, natural out.
__device__ __forceinline__ void fft32_dit_inv(float zr[32], float zi[32]) {
#pragma unroll
    for (int s = 4; s >= 0; s--) {            // len = 2, 4, ..., 32
        const int len = 32 >> s, half = len >> 1;
#pragma unroll
        for (int g = 0; g < 32; g += len)
#pragma unroll
            for (int j = 0; j < half; j++) {
                const int a = g + j, b = a + half;
                float tr, ti;
                rot<true>(j << s, zr[b], zi[b], tr, ti);
                zr[b] = zr[a] - tr; zi[b] = zi[a] - ti;
                zr[a] += tr;        zi[a] += ti;
            }
    }
}

// Forward half-pipeline: regs (lane=n2, reg i = n1, natural) ->
// regs (lane=k1, reg pos = br5(k2)) = X[k1 + 32*k2].
__device__ __forceinline__ void fwd_pipeline(float zr[32], float zi[32],
                                             float2* B, int lane,
                                             float bc, float bs) {
    fft32_dif<false>(zr, zi);                 // over n1; result at br5(k1)

    // mid twiddle e^{-2pi*i*lane*k1/1024} fused with transpose store (row=n2=lane, col=k1)
    B[lane * 33 + 0] = make_float2(zr[0], zi[0]);
    float cr = bc, ci = -bs;                  // w^1, w = e^{-2pi*i*lane/1024}
#pragma unroll
    for (int k1 = 1; k1 < 32; k1++) {
        const int r = br5(k1);
        float tr = fmaf(zr[r], cr, -zi[r] * ci);
        float ti = fmaf(zr[r], ci,  zi[r] * cr);
        B[lane * 33 + k1] = make_float2(tr, ti);
        float nr = fmaf(cr, bc,  ci * bs);    // cur *= (bc, -bs)
        float ni = fmaf(ci, bc, -cr * bs);
        cr = nr; ci = ni;
    }
    __syncwarp();
#pragma unroll
    for (int n2 = 0; n2 < 32; n2++) {         // transpose load: lane := k1
        float2 v = B[n2 * 33 + lane];
        zr[n2] = v.x; zi[n2] = v.y;
    }
    fft32_dif<false>(zr, zi);                 // over n2; result at br5(k2)
}

// ---------------- init kernel: Wc = conj(FFT(w))/N in pipeline layout ----------------

__global__ void k_wc(const float* __restrict__ wv) {
    __shared__ float2 B[32 * 33];
    const int lane = threadIdx.x;
    float zr[32], zi[32];
#pragma unroll
    for (int i = 0; i < 32; i++) { zr[i] = wv[32 * i + lane]; zi[i] = 0.0f; }
    float bs, bc;
    sincospif((float)lane * (1.0f / 512.0f), &bs, &bc);
    fwd_pipeline(zr, zi, B, lane, bc, bs);
#pragma unroll
    for (int m = 0; m < 32; m++)
        g_wc[(lane << 5) + m] = make_float2(zr[m] * (1.0f / 1024.0f),
                                            zi[m] * (-1.0f / 1024.0f));
}

// ---------------- main kernel ----------------

__global__ void __launch_bounds__(TPB) k_main(const float* __restrict__ x,
                                              float* __restrict__ out) {
    __shared__ float2 tb[WPB][32 * 33];
    const int lane = threadIdx.x & 31;
    const int wid  = threadIdx.x >> 5;
    float2* B = tb[wid];

    const long base = ((long)blockIdx.x * WPB + wid) * 2048;
    const float* __restrict__ xa = x + base;
    const float* __restrict__ xb = xa + 1024;

    float zr[32], zi[32];
#pragma unroll
    for (int i = 0; i < 32; i++) {            // coalesced: 128B line per instr
        zr[i] = xa[32 * i + lane];
        zi[i] = xb[32 * i + lane];
    }

    float bs, bc;
    sincospif((float)lane * (1.0f / 512.0f), &bs, &bc);

    fwd_pipeline(zr, zi, B, lane, bc, bs);    // lane=k1, reg pos=br5(k2)

    // pointwise: Z * conj(W)/N (identical layout from k_wc)
    const float4* wc4 = (const float4*)(g_wc + (lane << 5));
#pragma unroll
    for (int m = 0; m < 16; m++) {
        float4 v = wc4[m];
        {
            float a = zr[2 * m], b2 = zi[2 * m];
            zr[2 * m] = fmaf(a, v.x, -b2 * v.y);
            zi[2 * m] = fmaf(a, v.y,  b2 * v.x);
        }
        {
            float a = zr[2 * m + 1], b2 = zi[2 * m + 1];
            zr[2 * m + 1] = fmaf(a, v.z, -b2 * v.w);
            zi[2 * m + 1] = fmaf(a, v.w,  b2 * v.z);
        }
    }

    fft32_dit_inv(zr, zi);                    // over k2 (br in) -> natural n2

    __syncwarp();                             // transpose-1 loads done before overwrite
    // inverse mid twiddle e^{+2pi*i*n2*lane/1024} (lane = k1) fused with store (row=k1, col=n2)
    B[lane * 33 + 0] = make_float2(zr[0], zi[0]);
    {
        float cr = bc, ci = bs;               // w^1, w = e^{+2pi*i*lane/1024}
#pragma unroll
        for (int n2 = 1; n2 < 32; n2++) {
            float tr = fmaf(zr[n2], cr, -zi[n2] * ci);
            float ti = fmaf(zr[n2], ci,  zi[n2] * cr);
            B[lane * 33 + n2] = make_float2(tr, ti);
            float nr = fmaf(cr, bc, -ci * bs);    // cur *= (bc, +bs)
            float ni = fmaf(ci, bc,  cr * bs);
            cr = nr; ci = ni;
        }
    }
    __syncwarp();
#pragma unroll
    for (int k1 = 0; k1 < 32; k1++) {         // transpose load: lane := n2
        float2 v = B[k1 * 33 + lane];
        zr[k1] = v.x; zi[k1] = v.y;
    }
    fft32_dif<true>(zr, zi);                  // inverse over k1 -> y at br5(n1)

    // epilogue: mm at (lane=n2, reg br5(n1)) => token index 32*n1 + lane
    float* __restrict__ oa = out + base;
    float* __restrict__ ob = oa + 1024;
#pragma unroll
    for (int n1 = 0; n1 < 32; n1++) {
        const int r = br5(n1);
        float xav = xa[32 * n1 + lane];       // reload (L1-hot)
        float xbv = xb[32 * n1 + lane];
        oa[32 * n1 + lane] = fmaf(zr[r], xav, zr[r] + xav);  // mm*x + mm + x
        ob[32 * n1 + lane] = fmaf(zi[r], xbv, zi[r] + xbv);
    }
}

extern "C" void kernel_launch(void* const* d_in, const int* in_sizes, int n_in,
                              void* d_out, int out_size) {
    const float* x = (const float*)d_in[0];   // [65536, 1024] fp32
    const float* w = (const float*)d_in[1];   // [1024] fp32
    float* out = (float*)d_out;

    k_wc<<<1, 32>>>(w);
    k_main<<<NTOK / 2 / WPB, TPB>>>(x, out);
}

// round 6
// speedup vs baseline: 2.9268x; 1.1960x over previous
#include <cuda_runtime.h>

// circ_layer: out = mm*x + mm + x, mm[b,i] = sum_j x[b,j] * w[(j-i) mod 1024]
// = circular correlation => IDFT( FFT(x_row) * conj(FFT(w)) ), all fp32.
//
// Four-step FFT: 1024 = 32 x 32. One warp handles TWO tokens packed as one
// complex sequence (re = token a, im = token b). 32 complex values per thread
// in registers; compile-time twiddles for the length-32 FFTs; PRECOMPUTED
// mid-twiddle table (replaces the serial complex-multiply chains of R3);
// two 32x32 smem transposes per direction. No __syncthreads.

static constexpr int WPB  = 4;            // warps per block
static constexpr int TPB  = WPB * 32;
static constexpr int NTOK = 65536;

__device__ __align__(16) float2 g_wc[1024];    // conj(FFT(w))/N, pipeline layout
__device__ __align__(16) float2 g_mtw[1024];   // T[k*32+lane] = e^{-2pi*i*k*lane/1024}

__device__ __forceinline__ int br5(int x) {
    return ((x & 1) << 4) | ((x & 2) << 2) | (x & 4) | ((x & 8) >> 2) | ((x & 16) >> 4);
}

__device__ __forceinline__ float twc(int t) {
    constexpr float C[16] = {
        1.0f,                   0.9807852804032304f,  0.9238795325112867f,  0.8314696123025452f,
        0.7071067811865476f,    0.5555702330196022f,  0.3826834323650898f,  0.1950903220161283f,
        0.0f,                  -0.1950903220161283f, -0.3826834323650898f, -0.5555702330196022f,
       -0.7071067811865476f,   -0.8314696123025452f, -0.9238795325112867f, -0.9807852804032304f };
    return C[t];
}
__device__ __forceinline__ float tws(int t) {
    constexpr float S[16] = {
        0.0f,                   0.1950903220161283f,  0.3826834323650898f,  0.5555702330196022f,
        0.7071067811865476f,    0.8314696123025452f,  0.9238795325112867f,  0.9807852804032304f,
        1.0f,                   0.9807852804032304f,  0.9238795325112867f,  0.8314696123025452f,
        0.7071067811865476f,    0.5555702330196022f,  0.3826834323650898f,  0.1950903220161283f };
    return S[t];
}

// (xr,xi) = (dr,di) * e^{-+2*pi*i*t/32}  (forward: e^{-}, inverse: e^{+})
template<bool INV>
__device__ __forceinline__ void rot(int t, float dr, float di, float& xr, float& xi) {
    if (t == 0)      { xr = dr; xi = di; }
    else if (t == 8) {
        if (!INV) { xr = di;  xi = -dr; }   // * (-i)
        else      { xr = -di; xi =  dr; }   // * (+i)
    } else {
        float c = twc(t), s = tws(t);
        if (!INV) { xr = fmaf(dr, c,  di * s); xi = fmaf(di, c, -dr * s); }
        else      { xr = fmaf(dr, c, -di * s); xi = fmaf(di, c,  dr * s); }
    }
}

// DIF radix-2 length-32 FFT in registers: natural in, bit-reversed out.
template<bool INV>
__device__ __forceinline__ void fft32_dif(float zr[32], float zi[32]) {
#pragma unroll
    for (int s = 0; s < 5; s++) {
        const int len = 32 >> s, half = len >> 1;
#pragma unroll
        for (int g = 0; g < 32; g += len)
#pragma unroll
            for (int j = 0; j < half; j++) {
                const int a = g + j, b = a + half;
                float dr = zr[a] - zr[b], di = zi[a] - zi[b];
                zr[a] += zr[b]; zi[a] += zi[b];
                rot<INV>(j << s, dr, di, zr[b], zi[b]);
            }
    }
}

// DIT radix-2 length-32 inverse FFT: bit-reversed in, natural out.
__device__ __forceinline__ void fft32_dit_inv(float zr[32], float zi[32]) {
#pragma unroll
    for (int s = 4; s >= 0; s--) {            // len = 2, 4, ..., 32
        const int len = 32 >> s, half = len >> 1;
#pragma unroll
        for (int g = 0; g < 32; g += len)
#pragma unroll
            for (int j = 0; j < half; j++) {
                const int a = g + j, b = a + half;
                float tr, ti;
                rot<true>(j << s, zr[b], zi[b], tr, ti);
                zr[b] = zr[a] - tr; zi[b] = zi[a] - ti;
                zr[a] += tr;        zi[a] += ti;
            }
    }
}

// Forward half-pipeline: regs (lane=n2, reg i = n1, natural) ->
// regs (lane=k1, reg pos = br5(k2)) = X[k1 + 32*k2].
__device__ __forceinline__ void fwd_pipeline(float zr[32], float zi[32],
                                             float2* B, int lane) {
    fft32_dif<false>(zr, zi);                 // over n1; result at br5(k1)

    // mid twiddle e^{-2pi*i*lane*k1/1024} from table, fused with transpose
    // store (row=n2=lane, col=k1). Table is k-major -> coalesced warp loads.
    B[lane * 33 + 0] = make_float2(zr[0], zi[0]);
#pragma unroll
    for (int k1 = 1; k1 < 32; k1++) {
        const int r = br5(k1);
        float2 t = g_mtw[(k1 << 5) + lane];   // (cos, -sin)
        float tr = fmaf(zr[r], t.x, -zi[r] * t.y);
        float ti = fmaf(zi[r], t.x,  zr[r] * t.y);
        B[lane * 33 + k1] = make_float2(tr, ti);
    }
    __syncwarp();
#pragma unroll
    for (int n2 = 0; n2 < 32; n2++) {         // transpose load: lane := k1
        float2 v = B[n2 * 33 + lane];
        zr[n2] = v.x; zi[n2] = v.y;
    }
    fft32_dif<false>(zr, zi);                 // over n2; result at br5(k2)
}

// ---------------- init kernels ----------------

__global__ void k_mtw() {
    int i = blockIdx.x * blockDim.x + threadIdx.x;   // <<<4,256>>> -> 1024
    int k = i >> 5, lane = i & 31;
    int prod = (k * lane) & 1023;
    float s, c;
    sincospif((float)prod * (1.0f / 512.0f), &s, &c);
    g_mtw[i] = make_float2(c, -s);                   // e^{-2pi*i*k*lane/1024}
}

__global__ void k_wc(const float* __restrict__ wv) {
    __shared__ float2 B[32 * 33];
    const int lane = threadIdx.x;
    float zr[32], zi[32];
#pragma unroll
    for (int i = 0; i < 32; i++) { zr[i] = wv[32 * i + lane]; zi[i] = 0.0f; }
    fwd_pipeline(zr, zi, B, lane);
#pragma unroll
    for (int m = 0; m < 32; m++)
        g_wc[(lane << 5) + m] = make_float2(zr[m] * (1.0f / 1024.0f),
                                            zi[m] * (-1.0f / 1024.0f));
}

// ---------------- main kernel ----------------

__global__ void __launch_bounds__(TPB, 3) k_main(const float* __restrict__ x,
                                                 float* __restrict__ out) {
    __shared__ float2 tb[WPB][32 * 33];
    const int lane = threadIdx.x & 31;
    const int wid  = threadIdx.x >> 5;
    float2* B = tb[wid];

    const long base = ((long)blockIdx.x * WPB + wid) * 2048;
    const float* __restrict__ xa = x + base;
    const float* __restrict__ xb = xa + 1024;

    float zr[32], zi[32];
#pragma unroll
    for (int i = 0; i < 32; i++) {            // coalesced: 128B line per instr
        zr[i] = xa[32 * i + lane];
        zi[i] = xb[32 * i + lane];
    }

    fwd_pipeline(zr, zi, B, lane);            // lane=k1, reg pos=br5(k2)

    // pointwise: Z * conj(W)/N (identical layout from k_wc)
    const float4* wc4 = (const float4*)(g_wc + (lane << 5));
#pragma unroll
    for (int m = 0; m < 16; m++) {
        float4 v = wc4[m];
        {
            float a = zr[2 * m], b2 = zi[2 * m];
            zr[2 * m] = fmaf(a, v.x, -b2 * v.y);
            zi[2 * m] = fmaf(a, v.y,  b2 * v.x);
        }
        {
            float a = zr[2 * m + 1], b2 = zi[2 * m + 1];
            zr[2 * m + 1] = fmaf(a, v.z, -b2 * v.w);
            zi[2 * m + 1] = fmaf(a, v.w,  b2 * v.z);
        }
    }

    fft32_dit_inv(zr, zi);                    // over k2 (br in) -> natural n2

    __syncwarp();                             // transpose-1 loads done before overwrite
    // inverse mid twiddle e^{+2pi*i*n2*lane/1024} (lane = k1) = conj(table),
    // fused with transpose store (row=k1, col=n2)
    B[lane * 33 + 0] = make_float2(zr[0], zi[0]);
#pragma unroll
    for (int n2 = 1; n2 < 32; n2++) {
        float2 t = g_mtw[(n2 << 5) + lane];   // (cos, -sin); conj => (cos, +sin)
        float tr = fmaf(zr[n2], t.x,  zi[n2] * t.y);
        float ti = fmaf(zi[n2], t.x, -zr[n2] * t.y);
        B[lane * 33 + n2] = make_float2(tr, ti);
    }
    __syncwarp();
#pragma unroll
    for (int k1 = 0; k1 < 32; k1++) {         // transpose load: lane := n2
        float2 v = B[k1 * 33 + lane];
        zr[k1] = v.x; zi[k1] = v.y;
    }
    fft32_dif<true>(zr, zi);                  // inverse over k1 -> y at br5(n1)

    // epilogue: mm at (lane=n2, reg br5(n1)) => token index 32*n1 + lane
    float* __restrict__ oa = out + base;
    float* __restrict__ ob = oa + 1024;
#pragma unroll
    for (int n1 = 0; n1 < 32; n1++) {
        const int r = br5(n1);
        float xav = xa[32 * n1 + lane];       // reload (L1-hot)
        float xbv = xb[32 * n1 + lane];
        oa[32 * n1 + lane] = fmaf(zr[r], xav, zr[r] + xav);  // mm*x + mm + x
        ob[32 * n1 + lane] = fmaf(zi[r], xbv, zi[r] + xbv);
    }
}

extern "C" void kernel_launch(void* const* d_in, const int* in_sizes, int n_in,
                              void* d_out, int out_size) {
    const float* x = (const float*)d_in[0];   // [65536, 1024] fp32
    const float* w = (const float*)d_in[1];   // [1024] fp32
    float* out = (float*)d_out;

    k_mtw<<<4, 256>>>();
    k_wc<<<1, 32>>>(w);
    k_main<<<NTOK / 2 / WPB, TPB>>>(x, out);
}